// round 2
// baseline (speedup 1.0000x reference)
#include <cuda_runtime.h>
#include <math.h>

#define HH 8
#define HD 32
#define BB 4
#define NN 2048
#define DD 256
#define BH (BB*HH)   // 32

// ---- device scratch (static: allocation-free rule) ----
__device__ float g_Q[(size_t)BH*NN*HD];
__device__ float g_K[(size_t)BH*NN*HD];
__device__ float g_P[(size_t)BH*NN*NN];     // unnormalized exp(S), 512 MB
__device__ float g_rowsum[BH*NN];
__device__ float g_t0[(size_t)BH*NN*HD];
__device__ float g_t1[(size_t)BH*NN*HD];
__device__ float g_acc[(size_t)BH*NN*HD];

__device__ __forceinline__ float2 unpack2(unsigned long long v) {
    float2 f;
    asm("mov.b64 {%0, %1}, %2;" : "=f"(f.x), "=f"(f.y) : "l"(v));
    return f;
}

#define FMA2(acc, a, b) \
    asm("fma.rn.f32x2 %0, %1, %2, %0;" : "+l"(acc) : "l"(a), "l"(b))

// ============================================================
// Kernel 1: QKV projection + head split.
// grid (128, 4, 3): 64-row x 64-col tiles, z = which matrix.
// ============================================================
__global__ void qkv_kernel(const float* __restrict__ x,
                           const float* __restrict__ Wq, const float* __restrict__ bq,
                           const float* __restrict__ Wk, const float* __restrict__ bk,
                           const float* __restrict__ Wv, const float* __restrict__ bv,
                           const float* __restrict__ coeffs) {
    const int mat = blockIdx.z;
    const float* W    = (mat == 0) ? Wq : ((mat == 1) ? Wk : Wv);
    const float* bias = (mat == 0) ? bq : ((mat == 1) ? bk : bv);
    const int m0 = blockIdx.x * 64;
    const int c0 = blockIdx.y * 64;

    __shared__ float Xs[64][33];
    __shared__ float Ws[32][64];

    const int tid = threadIdx.x;
    const int ty = tid >> 4, tx = tid & 15;

    float acc[4][4] = {};

    for (int k0 = 0; k0 < DD; k0 += 32) {
        for (int l = tid; l < 512; l += 256) {
            int r = l >> 3, kq = l & 7;
            float4 v = *(const float4*)(x + (size_t)(m0 + r) * DD + k0 + kq * 4);
            Xs[r][kq*4+0] = v.x; Xs[r][kq*4+1] = v.y;
            Xs[r][kq*4+2] = v.z; Xs[r][kq*4+3] = v.w;
        }
        for (int l = tid; l < 512; l += 256) {
            int k = l >> 4, cq = l & 15;
            *(float4*)&Ws[k][cq*4] = *(const float4*)(W + (size_t)(k0 + k) * DD + c0 + cq * 4);
        }
        __syncthreads();
        #pragma unroll
        for (int kk = 0; kk < 32; kk++) {
            float a0 = Xs[ty*4+0][kk];
            float a1 = Xs[ty*4+1][kk];
            float a2 = Xs[ty*4+2][kk];
            float a3 = Xs[ty*4+3][kk];
            float4 b = *(float4*)&Ws[kk][tx*4];
            acc[0][0] += a0*b.x; acc[0][1] += a0*b.y; acc[0][2] += a0*b.z; acc[0][3] += a0*b.w;
            acc[1][0] += a1*b.x; acc[1][1] += a1*b.y; acc[1][2] += a1*b.z; acc[1][3] += a1*b.w;
            acc[2][0] += a2*b.x; acc[2][1] += a2*b.y; acc[2][2] += a2*b.z; acc[2][3] += a2*b.w;
            acc[3][0] += a3*b.x; acc[3][1] += a3*b.y; acc[3][2] += a3*b.z; acc[3][3] += a3*b.w;
        }
        __syncthreads();
    }

    #pragma unroll
    for (int i = 0; i < 4; i++) {
        int m = m0 + ty * 4 + i;
        int b_ = m >> 11, n = m & 2047;
        #pragma unroll
        for (int j = 0; j < 4; j++) {
            int c = c0 + tx * 4 + j;
            float val = acc[i][j] + bias[c];
            int h = c >> 5, d = c & 31;
            size_t idx = ((size_t)(b_ * HH + h) * NN + n) * HD + d;
            if (mat == 0)      g_Q[idx] = val;
            else if (mat == 1) g_K[idx] = val;
            else {
                g_t0[idx]  = val;
                g_acc[idx] = coeffs[h * 4] * val;   // c0 * v
            }
        }
    }
}

// ============================================================
// Kernel 2: P = exp(Q K^T * scale) + rowsums. f32x2 packed over k-pairs.
// grid (32 row-tiles of 64, 32 bh), block 256.
// Per thread: 4 rows (rg + 16i) x 8 cols (cx + 16j), acc packed (even-k, odd-k).
// ============================================================
__global__ void attnP_kernel() {
    const int bh = blockIdx.y;
    const int r0 = blockIdx.x * 64;

    __shared__ float Qs[64][36];
    __shared__ float Ks[128][36];
    __shared__ float s_rowsum[64];

    const int tid = threadIdx.x;
    const int rg = tid >> 4;   // 0..15
    const int cx = tid & 15;   // 0..15

    const float* Qb = g_Q + ((size_t)bh * NN + r0) * HD;
    for (int l = tid; l < 512; l += 256) {          // 64 rows * 8 float4
        int r = l >> 3, kq = l & 7;
        *(float4*)&Qs[r][kq*4] = *(const float4*)(Qb + (size_t)r * HD + kq * 4);
    }
    if (tid < 64) s_rowsum[tid] = 0.f;
    __syncthreads();

    const float scale = 0.17677669529663687f;     // 1/sqrt(32)

    for (int ct = 0; ct < 16; ct++) {
        const int c0 = ct * 128;
        const float* Kb = g_K + ((size_t)bh * NN + c0) * HD;
        for (int l = tid; l < 1024; l += 256) {     // 128 rows * 8 float4
            int r = l >> 3, kq = l & 7;
            *(float4*)&Ks[r][kq*4] = *(const float4*)(Kb + (size_t)r * HD + kq * 4);
        }
        __syncthreads();

        unsigned long long acc2[4][8];
        #pragma unroll
        for (int i = 0; i < 4; i++)
            #pragma unroll
            for (int j = 0; j < 8; j++) acc2[i][j] = 0ULL;

        #pragma unroll
        for (int kq = 0; kq < 8; kq++) {
            ulonglong2 pr[4];
            #pragma unroll
            for (int i = 0; i < 4; i++)
                pr[i] = *(const ulonglong2*)&Qs[rg + 16*i][kq*4];
            #pragma unroll
            for (int j = 0; j < 8; j++) {
                ulonglong2 tc = *(const ulonglong2*)&Ks[cx + 16*j][kq*4];
                #pragma unroll
                for (int i = 0; i < 4; i++) {
                    FMA2(acc2[i][j], pr[i].x, tc.x);
                    FMA2(acc2[i][j], pr[i].y, tc.y);
                }
            }
        }

        float* Pb = g_P + ((size_t)bh * NN + r0) * NN + c0;
        #pragma unroll
        for (int i = 0; i < 4; i++) {
            int row = rg + 16*i;
            float rs = 0.f;
            #pragma unroll
            for (int j = 0; j < 8; j++) {
                float2 u = unpack2(acc2[i][j]);
                float e = __expf((u.x + u.y) * scale);
                Pb[(size_t)row * NN + cx + 16*j] = e;
                rs += e;
            }
            // reduce across the 16 cx lanes (same rg half-warp)
            rs += __shfl_xor_sync(0xffffffffu, rs, 1);
            rs += __shfl_xor_sync(0xffffffffu, rs, 2);
            rs += __shfl_xor_sync(0xffffffffu, rs, 4);
            rs += __shfl_xor_sync(0xffffffffu, rs, 8);
            if (cx == 0) s_rowsum[row] += rs;
        }
        __syncthreads();
    }

    if (tid < 64) g_rowsum[bh * NN + r0 + tid] = s_rowsum[tid];
}

// ============================================================
// Kernel 3: t_out = diag(1/rowsum) * P * t_in ; g_acc += c_k * t_out
// f32x2 packed over m-pairs. grid (16 row-tiles of 128, 32 bh), block 256.
// Per thread: 4 rows (rg + 32i) x 4 cols (cx + 8j).
// ============================================================
__global__ void pass_kernel(const float* __restrict__ coeffs, int pass) {
    const float* tin  = (pass & 1) ? g_t0 : g_t1;
    float*       tout = (pass & 1) ? g_t1 : g_t0;

    const int bh = blockIdx.y;
    const int r0 = blockIdx.x * 128;
    const float c = coeffs[(bh & 7) * 4 + pass];

    __shared__ float Ps[128][68];    // P tile, row-major [row][m]
    __shared__ float Tst[32][68];    // t tile transposed [col][m]

    const int tid = threadIdx.x;
    const int rg = tid >> 3;      // 0..31
    const int cx = tid & 7;       // 0..7

    unsigned long long acc2[4][4];
    #pragma unroll
    for (int i = 0; i < 4; i++)
        #pragma unroll
        for (int j = 0; j < 4; j++) acc2[i][j] = 0ULL;

    const float* Prow = g_P + ((size_t)bh * NN + r0) * NN;
    const float* Tb   = tin + (size_t)bh * NN * HD;

    for (int m0 = 0; m0 < NN; m0 += 64) {
        for (int l = tid; l < 2048; l += 256) {       // 128 rows * 16 float4 along m
            int r = l >> 4, mq = l & 15;
            *(float4*)&Ps[r][mq*4] = *(const float4*)(Prow + (size_t)r * NN + m0 + mq * 4);
        }
        for (int l = tid; l < 512; l += 256) {        // 64 m-rows * 8 float4, transposed
            int m = l >> 3, cq = l & 7;
            float4 v = *(const float4*)(Tb + (size_t)(m0 + m) * HD + cq * 4);
            Tst[cq*4+0][m] = v.x; Tst[cq*4+1][m] = v.y;
            Tst[cq*4+2][m] = v.z; Tst[cq*4+3][m] = v.w;
        }
        __syncthreads();

        #pragma unroll
        for (int mq = 0; mq < 16; mq++) {
            ulonglong2 pr[4], tc[4];
            #pragma unroll
            for (int i = 0; i < 4; i++)
                pr[i] = *(const ulonglong2*)&Ps[rg + 32*i][mq*4];
            #pragma unroll
            for (int j = 0; j < 4; j++)
                tc[j] = *(const ulonglong2*)&Tst[cx + 8*j][mq*4];
            #pragma unroll
            for (int i = 0; i < 4; i++)
                #pragma unroll
                for (int j = 0; j < 4; j++) {
                    FMA2(acc2[i][j], pr[i].x, tc[j].x);
                    FMA2(acc2[i][j], pr[i].y, tc[j].y);
                }
        }
        __syncthreads();
    }

    #pragma unroll
    for (int i = 0; i < 4; i++) {
        int row = r0 + rg + 32*i;
        float inv = 1.0f / g_rowsum[bh * NN + row];
        #pragma unroll
        for (int j = 0; j < 4; j++) {
            float2 u = unpack2(acc2[i][j]);
            float s = (u.x + u.y) * inv;
            size_t o = ((size_t)bh * NN + row) * HD + cx + 8*j;
            tout[o] = s;
            g_acc[o] += c * s;
        }
    }
}

// ============================================================
// Kernel 4: out = merged(g_acc) @ Wo + bo
// grid (128, 4), block 256.
// ============================================================
__global__ void outproj_kernel(const float* __restrict__ Wo,
                               const float* __restrict__ bo,
                               float* __restrict__ out) {
    const int m0 = blockIdx.x * 64;
    const int c0 = blockIdx.y * 64;

    __shared__ float Ms[64][33];
    __shared__ float Ws[32][64];

    const int tid = threadIdx.x;
    const int ty = tid >> 4, tx = tid & 15;

    float acc[4][4] = {};

    for (int k0 = 0; k0 < DD; k0 += 32) {
        int hh = k0 >> 5;                 // one head per 32-wide k tile
        for (int l = tid; l < 512; l += 256) {
            int r = l >> 3, kq = l & 7;
            int m = m0 + r;
            int b_ = m >> 11, n = m & 2047;
            float4 v = *(const float4*)(g_acc + ((size_t)(b_ * HH + hh) * NN + n) * HD + kq * 4);
            Ms[r][kq*4+0] = v.x; Ms[r][kq*4+1] = v.y;
            Ms[r][kq*4+2] = v.z; Ms[r][kq*4+3] = v.w;
        }
        for (int l = tid; l < 512; l += 256) {
            int k = l >> 4, cq = l & 15;
            *(float4*)&Ws[k][cq*4] = *(const float4*)(Wo + (size_t)(k0 + k) * DD + c0 + cq * 4);
        }
        __syncthreads();
        #pragma unroll
        for (int kk = 0; kk < 32; kk++) {
            float a0 = Ms[ty*4+0][kk];
            float a1 = Ms[ty*4+1][kk];
            float a2 = Ms[ty*4+2][kk];
            float a3 = Ms[ty*4+3][kk];
            float4 b = *(float4*)&Ws[kk][tx*4];
            acc[0][0] += a0*b.x; acc[0][1] += a0*b.y; acc[0][2] += a0*b.z; acc[0][3] += a0*b.w;
            acc[1][0] += a1*b.x; acc[1][1] += a1*b.y; acc[1][2] += a1*b.z; acc[1][3] += a1*b.w;
            acc[2][0] += a2*b.x; acc[2][1] += a2*b.y; acc[2][2] += a2*b.z; acc[2][3] += a2*b.w;
            acc[3][0] += a3*b.x; acc[3][1] += a3*b.y; acc[3][2] += a3*b.z; acc[3][3] += a3*b.w;
        }
        __syncthreads();
    }

    #pragma unroll
    for (int i = 0; i < 4; i++) {
        int m = m0 + ty * 4 + i;
        #pragma unroll
        for (int j = 0; j < 4; j++) {
            int cc = c0 + tx * 4 + j;
            out[(size_t)m * DD + cc] = acc[i][j] + bo[cc];
        }
    }
}

// ============================================================
extern "C" void kernel_launch(void* const* d_in, const int* in_sizes, int n_in,
                              void* d_out, int out_size) {
    const float* x      = (const float*)d_in[0];
    const float* Wq     = (const float*)d_in[1];
    const float* bq     = (const float*)d_in[2];
    const float* Wk     = (const float*)d_in[3];
    const float* bk     = (const float*)d_in[4];
    const float* Wv     = (const float*)d_in[5];
    const float* bv     = (const float*)d_in[6];
    const float* Wo     = (const float*)d_in[7];
    const float* bo     = (const float*)d_in[8];
    const float* coeffs = (const float*)d_in[9];
    float* out = (float*)d_out;

    dim3 g1(128, 4, 3);
    qkv_kernel<<<g1, 256>>>(x, Wq, bq, Wk, bk, Wv, bv, coeffs);

    dim3 g2(32, 32);
    attnP_kernel<<<g2, 256>>>();

    dim3 g3(16, 32);
    pass_kernel<<<g3, 256>>>(coeffs, 1);
    pass_kernel<<<g3, 256>>>(coeffs, 2);
    pass_kernel<<<g3, 256>>>(coeffs, 3);

    dim3 g4(128, 4);
    outproj_kernel<<<g4, 256>>>(Wo, bo, out);
}

// round 4
// speedup vs baseline: 1.8401x; 1.8401x over previous
#include <cuda_runtime.h>
#include <math.h>
#include <stdint.h>

#define HH 8
#define HD 32
#define BB 4
#define NN 2048
#define DD 256
#define BH (BB*HH)   // 32

// ---- device scratch (static: allocation-free rule) ----
__device__ float g_Q[(size_t)BH*NN*HD];
__device__ float g_K[(size_t)BH*NN*HD];
__device__ float g_P[(size_t)BH*NN*NN];     // unnormalized exp(S), 512 MB
__device__ float g_rowsum[BH*NN];
__device__ float g_t0[(size_t)BH*NN*HD];
__device__ float g_t1[(size_t)BH*NN*HD];
__device__ float g_acc[(size_t)BH*NN*HD];

__device__ __forceinline__ uint32_t f2tf(float f) {
    uint32_t r;
    asm("cvt.rna.tf32.f32 %0, %1;" : "=r"(r) : "f"(f));
    return r;
}

__device__ __forceinline__ void mma_tf32(float& d0, float& d1, float& d2, float& d3,
                                         uint32_t a0, uint32_t a1, uint32_t a2, uint32_t a3,
                                         uint32_t b0, uint32_t b1) {
    asm("mma.sync.aligned.m16n8k8.row.col.f32.tf32.tf32.f32 "
        "{%0,%1,%2,%3},{%4,%5,%6,%7},{%8,%9},{%0,%1,%2,%3};"
        : "+f"(d0), "+f"(d1), "+f"(d2), "+f"(d3)
        : "r"(a0), "r"(a1), "r"(a2), "r"(a3), "r"(b0), "r"(b1));
}

// ============================================================
// Kernel 1: QKV projection + head split. (scalar fp32 — small)
// grid (128, 4, 3): 64-row x 64-col tiles, z = which matrix.
// ============================================================
__global__ void qkv_kernel(const float* __restrict__ x,
                           const float* __restrict__ Wq, const float* __restrict__ bq,
                           const float* __restrict__ Wk, const float* __restrict__ bk,
                           const float* __restrict__ Wv, const float* __restrict__ bv,
                           const float* __restrict__ coeffs) {
    const int mat = blockIdx.z;
    const float* W    = (mat == 0) ? Wq : ((mat == 1) ? Wk : Wv);
    const float* bias = (mat == 0) ? bq : ((mat == 1) ? bk : bv);
    const int m0 = blockIdx.x * 64;
    const int c0 = blockIdx.y * 64;

    __shared__ float Xs[64][33];
    __shared__ float Ws[32][64];

    const int tid = threadIdx.x;
    const int ty = tid >> 4, tx = tid & 15;

    float acc[4][4] = {};

    for (int k0 = 0; k0 < DD; k0 += 32) {
        for (int l = tid; l < 512; l += 256) {
            int r = l >> 3, kq = l & 7;
            float4 v = *(const float4*)(x + (size_t)(m0 + r) * DD + k0 + kq * 4);
            Xs[r][kq*4+0] = v.x; Xs[r][kq*4+1] = v.y;
            Xs[r][kq*4+2] = v.z; Xs[r][kq*4+3] = v.w;
        }
        for (int l = tid; l < 512; l += 256) {
            int k = l >> 4, cq = l & 15;
            *(float4*)&Ws[k][cq*4] = *(const float4*)(W + (size_t)(k0 + k) * DD + c0 + cq * 4);
        }
        __syncthreads();
        #pragma unroll
        for (int kk = 0; kk < 32; kk++) {
            float a0 = Xs[ty*4+0][kk];
            float a1 = Xs[ty*4+1][kk];
            float a2 = Xs[ty*4+2][kk];
            float a3 = Xs[ty*4+3][kk];
            float4 b = *(float4*)&Ws[kk][tx*4];
            acc[0][0] += a0*b.x; acc[0][1] += a0*b.y; acc[0][2] += a0*b.z; acc[0][3] += a0*b.w;
            acc[1][0] += a1*b.x; acc[1][1] += a1*b.y; acc[1][2] += a1*b.z; acc[1][3] += a1*b.w;
            acc[2][0] += a2*b.x; acc[2][1] += a2*b.y; acc[2][2] += a2*b.z; acc[2][3] += a2*b.w;
            acc[3][0] += a3*b.x; acc[3][1] += a3*b.y; acc[3][2] += a3*b.z; acc[3][3] += a3*b.w;
        }
        __syncthreads();
    }

    #pragma unroll
    for (int i = 0; i < 4; i++) {
        int m = m0 + ty * 4 + i;
        int b_ = m >> 11, n = m & 2047;
        #pragma unroll
        for (int j = 0; j < 4; j++) {
            int c = c0 + tx * 4 + j;
            float val = acc[i][j] + bias[c];
            int h = c >> 5, d = c & 31;
            size_t idx = ((size_t)(b_ * HH + h) * NN + n) * HD + d;
            if (mat == 0)      g_Q[idx] = val;
            else if (mat == 1) g_K[idx] = val;
            else {
                g_t0[idx]  = val;
                g_acc[idx] = coeffs[h * 4] * val;   // c0 * v
            }
        }
    }
}

// ============================================================
// Kernel 2: P = exp(Q K^T * scale) + rowsums, via tf32 mma.sync.
// grid (16 row-tiles of 128, 32 bh), block 256 (8 warps).
// Warp w: rows [w*16, w*16+16), all 128 cols of the ct-chunk.
// ============================================================
__global__ void attnP_kernel() {
    const int bh = blockIdx.y;
    const int r0 = blockIdx.x * 128;

    __shared__ uint32_t Qs[128][36];   // tf32 bits; bank = (4r+c)%32 conflict-free
    __shared__ uint32_t Ks[128][36];

    const int tid  = threadIdx.x;
    const int warp = tid >> 5;
    const int lane = tid & 31;
    const int g  = lane >> 2;   // 0..7
    const int qd = lane & 3;    // 0..3

    const float scale = 0.17677669529663687f;  // 1/sqrt(32), folded into Q

    // stage Q (scaled, tf32-rounded): 128x32 = 1024 float4
    const float* Qb = g_Q + ((size_t)bh * NN + r0) * HD;
    for (int l = tid; l < 1024; l += 256) {
        int r = l >> 3, kq = l & 7;
        float4 v = *(const float4*)(Qb + (size_t)r * HD + kq * 4);
        uint4 u;
        u.x = f2tf(v.x * scale); u.y = f2tf(v.y * scale);
        u.z = f2tf(v.z * scale); u.w = f2tf(v.w * scale);
        *(uint4*)&Qs[r][kq*4] = u;
    }
    __syncthreads();

    const int row_l = warp * 16 + g;      // local row for this lane's frags
    float rs_lo = 0.f, rs_hi = 0.f;       // rowsum accumulators (rows row_l, row_l+8)

    for (int ct = 0; ct < 16; ct++) {
        const int c0 = ct * 128;
        const float* Kb = g_K + ((size_t)bh * NN + c0) * HD;
        for (int l = tid; l < 1024; l += 256) {
            int r = l >> 3, kq = l & 7;
            float4 v = *(const float4*)(Kb + (size_t)r * HD + kq * 4);
            uint4 u;
            u.x = f2tf(v.x); u.y = f2tf(v.y);
            u.z = f2tf(v.z); u.w = f2tf(v.w);
            *(uint4*)&Ks[r][kq*4] = u;
        }
        __syncthreads();

        float acc[16][4];
        #pragma unroll
        for (int j = 0; j < 16; j++) {
            acc[j][0] = 0.f; acc[j][1] = 0.f; acc[j][2] = 0.f; acc[j][3] = 0.f;
        }

        #pragma unroll
        for (int kc = 0; kc < 32; kc += 8) {
            uint32_t a0 = Qs[row_l    ][kc + qd];
            uint32_t a1 = Qs[row_l + 8][kc + qd];
            uint32_t a2 = Qs[row_l    ][kc + qd + 4];
            uint32_t a3 = Qs[row_l + 8][kc + qd + 4];
            #pragma unroll
            for (int j = 0; j < 16; j++) {
                uint32_t b0 = Ks[j*8 + g][kc + qd];
                uint32_t b1 = Ks[j*8 + g][kc + qd + 4];
                mma_tf32(acc[j][0], acc[j][1], acc[j][2], acc[j][3],
                         a0, a1, a2, a3, b0, b1);
            }
        }

        // epilogue: exp + store + rowsum partials
        float* Pb = g_P + ((size_t)bh * NN + r0) * NN + c0;
        #pragma unroll
        for (int j = 0; j < 16; j++) {
            int col = j*8 + qd*2;
            float e0 = __expf(acc[j][0]);
            float e1 = __expf(acc[j][1]);
            float e2 = __expf(acc[j][2]);
            float e3 = __expf(acc[j][3]);
            float2 lo = make_float2(e0, e1);
            float2 hi = make_float2(e2, e3);
            *(float2*)(Pb + (size_t)(row_l    ) * NN + col) = lo;
            *(float2*)(Pb + (size_t)(row_l + 8) * NN + col) = hi;
            rs_lo += e0 + e1;
            rs_hi += e2 + e3;
        }
        __syncthreads();
    }

    // reduce rowsums over the 4 qd lanes (same row group)
    rs_lo += __shfl_xor_sync(0xffffffffu, rs_lo, 1);
    rs_lo += __shfl_xor_sync(0xffffffffu, rs_lo, 2);
    rs_hi += __shfl_xor_sync(0xffffffffu, rs_hi, 1);
    rs_hi += __shfl_xor_sync(0xffffffffu, rs_hi, 2);
    if (qd == 0) {
        g_rowsum[bh * NN + r0 + row_l]     = rs_lo;
        g_rowsum[bh * NN + r0 + row_l + 8] = rs_hi;
    }
}

// ============================================================
// Kernel 3: t_out = diag(1/rowsum) * P * t_in ; g_acc += c_k * t_out
// tf32 mma.sync. grid (16 row-tiles of 128, 32 bh), block 256 (8 warps).
// Warp w: rows [w*16, w*16+16), all 32 cols. K chunks of 64.
// ============================================================
__global__ void pass_kernel(const float* __restrict__ coeffs, int pass) {
    const float* tin  = (pass & 1) ? g_t0 : g_t1;
    float*       tout = (pass & 1) ? g_t1 : g_t0;

    const int bh = blockIdx.y;
    const int r0 = blockIdx.x * 128;
    const float c = coeffs[(bh & 7) * 4 + pass];

    __shared__ uint32_t Ps[128][68];   // bank = (4r+c)%32 conflict-free for A frags
    __shared__ uint32_t Ts[64][40];    // bank = (8k+n)%32 conflict-free for B frags

    const int tid  = threadIdx.x;
    const int warp = tid >> 5;
    const int lane = tid & 31;
    const int g  = lane >> 2;
    const int qd = lane & 3;

    float acc[4][4];
    #pragma unroll
    for (int j = 0; j < 4; j++) {
        acc[j][0] = 0.f; acc[j][1] = 0.f; acc[j][2] = 0.f; acc[j][3] = 0.f;
    }

    const float* Prow = g_P + ((size_t)bh * NN + r0) * NN;
    const float* Tb   = tin + (size_t)bh * NN * HD;
    const int row_l = warp * 16 + g;

    for (int m0 = 0; m0 < NN; m0 += 64) {
        // stage P tile 128x64: 2048 float4
        for (int l = tid; l < 2048; l += 256) {
            int r = l >> 4, mq = l & 15;
            float4 v = *(const float4*)(Prow + (size_t)r * NN + m0 + mq * 4);
            uint4 u;
            u.x = f2tf(v.x); u.y = f2tf(v.y);
            u.z = f2tf(v.z); u.w = f2tf(v.w);
            *(uint4*)&Ps[r][mq*4] = u;
        }
        // stage t tile 64x32: 512 float4 (natural [m][col] layout)
        for (int l = tid; l < 512; l += 256) {
            int m = l >> 3, cq = l & 7;
            float4 v = *(const float4*)(Tb + (size_t)(m0 + m) * HD + cq * 4);
            uint4 u;
            u.x = f2tf(v.x); u.y = f2tf(v.y);
            u.z = f2tf(v.z); u.w = f2tf(v.w);
            *(uint4*)&Ts[m][cq*4] = u;
        }
        __syncthreads();

        #pragma unroll
        for (int kc = 0; kc < 64; kc += 8) {
            uint32_t a0 = Ps[row_l    ][kc + qd];
            uint32_t a1 = Ps[row_l + 8][kc + qd];
            uint32_t a2 = Ps[row_l    ][kc + qd + 4];
            uint32_t a3 = Ps[row_l + 8][kc + qd + 4];
            #pragma unroll
            for (int j = 0; j < 4; j++) {
                uint32_t b0 = Ts[kc + qd    ][j*8 + g];
                uint32_t b1 = Ts[kc + qd + 4][j*8 + g];
                mma_tf32(acc[j][0], acc[j][1], acc[j][2], acc[j][3],
                         a0, a1, a2, a3, b0, b1);
            }
        }
        __syncthreads();
    }

    // epilogue: normalize, write tout + g_acc
    const int r_lo = r0 + row_l;
    const int r_hi = r_lo + 8;
    const float inv_lo = 1.0f / g_rowsum[bh * NN + r_lo];
    const float inv_hi = 1.0f / g_rowsum[bh * NN + r_hi];
    #pragma unroll
    for (int j = 0; j < 4; j++) {
        int col = j*8 + qd*2;
        size_t o_lo = ((size_t)bh * NN + r_lo) * HD + col;
        size_t o_hi = ((size_t)bh * NN + r_hi) * HD + col;
        float2 lo = make_float2(acc[j][0] * inv_lo, acc[j][1] * inv_lo);
        float2 hi = make_float2(acc[j][2] * inv_hi, acc[j][3] * inv_hi);
        *(float2*)(tout + o_lo) = lo;
        *(float2*)(tout + o_hi) = hi;
        float2 a_lo = *(float2*)(g_acc + o_lo);
        float2 a_hi = *(float2*)(g_acc + o_hi);
        a_lo.x += c * lo.x; a_lo.y += c * lo.y;
        a_hi.x += c * hi.x; a_hi.y += c * hi.y;
        *(float2*)(g_acc + o_lo) = a_lo;
        *(float2*)(g_acc + o_hi) = a_hi;
    }
}

// ============================================================
// Kernel 4: out = merged(g_acc) @ Wo + bo  (scalar fp32 — small)
// grid (128, 4), block 256.
// ============================================================
__global__ void outproj_kernel(const float* __restrict__ Wo,
                               const float* __restrict__ bo,
                               float* __restrict__ out) {
    const int m0 = blockIdx.x * 64;
    const int c0 = blockIdx.y * 64;

    __shared__ float Ms[64][33];
    __shared__ float Ws[32][64];

    const int tid = threadIdx.x;
    const int ty = tid >> 4, tx = tid & 15;

    float acc[4][4] = {};

    for (int k0 = 0; k0 < DD; k0 += 32) {
        int hh = k0 >> 5;                 // one head per 32-wide k tile
        for (int l = tid; l < 512; l += 256) {
            int r = l >> 3, kq = l & 7;
            int m = m0 + r;
            int b_ = m >> 11, n = m & 2047;
            float4 v = *(const float4*)(g_acc + ((size_t)(b_ * HH + hh) * NN + n) * HD + kq * 4);
            Ms[r][kq*4+0] = v.x; Ms[r][kq*4+1] = v.y;
            Ms[r][kq*4+2] = v.z; Ms[r][kq*4+3] = v.w;
        }
        for (int l = tid; l < 512; l += 256) {
            int k = l >> 4, cq = l & 15;
            *(float4*)&Ws[k][cq*4] = *(const float4*)(Wo + (size_t)(k0 + k) * DD + c0 + cq * 4);
        }
        __syncthreads();
        #pragma unroll
        for (int kk = 0; kk < 32; kk++) {
            float a0 = Ms[ty*4+0][kk];
            float a1 = Ms[ty*4+1][kk];
            float a2 = Ms[ty*4+2][kk];
            float a3 = Ms[ty*4+3][kk];
            float4 b = *(float4*)&Ws[kk][tx*4];
            acc[0][0] += a0*b.x; acc[0][1] += a0*b.y; acc[0][2] += a0*b.z; acc[0][3] += a0*b.w;
            acc[1][0] += a1*b.x; acc[1][1] += a1*b.y; acc[1][2] += a1*b.z; acc[1][3] += a1*b.w;
            acc[2][0] += a2*b.x; acc[2][1] += a2*b.y; acc[2][2] += a2*b.z; acc[2][3] += a2*b.w;
            acc[3][0] += a3*b.x; acc[3][1] += a3*b.y; acc[3][2] += a3*b.z; acc[3][3] += a3*b.w;
        }
        __syncthreads();
    }

    #pragma unroll
    for (int i = 0; i < 4; i++) {
        int m = m0 + ty * 4 + i;
        #pragma unroll
        for (int j = 0; j < 4; j++) {
            int cc = c0 + tx * 4 + j;
            out[(size_t)m * DD + cc] = acc[i][j] + bo[cc];
        }
    }
}

// ============================================================
extern "C" void kernel_launch(void* const* d_in, const int* in_sizes, int n_in,
                              void* d_out, int out_size) {
    const float* x      = (const float*)d_in[0];
    const float* Wq     = (const float*)d_in[1];
    const float* bq     = (const float*)d_in[2];
    const float* Wk     = (const float*)d_in[3];
    const float* bk     = (const float*)d_in[4];
    const float* Wv     = (const float*)d_in[5];
    const float* bv     = (const float*)d_in[6];
    const float* Wo     = (const float*)d_in[7];
    const float* bo     = (const float*)d_in[8];
    const float* coeffs = (const float*)d_in[9];
    float* out = (float*)d_out;

    dim3 g1(128, 4, 3);
    qkv_kernel<<<g1, 256>>>(x, Wq, bq, Wk, bk, Wv, bv, coeffs);

    dim3 g2(16, 32);
    attnP_kernel<<<g2, 256>>>();

    pass_kernel<<<g2, 256>>>(coeffs, 1);
    pass_kernel<<<g2, 256>>>(coeffs, 2);
    pass_kernel<<<g2, 256>>>(coeffs, 3);

    dim3 g4(128, 4);
    outproj_kernel<<<g4, 256>>>(Wo, bo, out);
}

// round 5
// speedup vs baseline: 2.7307x; 1.4840x over previous
#include <cuda_runtime.h>
#include <math.h>
#include <stdint.h>

#define HH 8
#define HD 32
#define BB 4
#define NN 2048
#define DD 256
#define BH (BB*HH)   // 32

// ---- device scratch (static: allocation-free rule) ----
__device__ float g_Q[(size_t)BH*NN*HD];
__device__ float g_K[(size_t)BH*NN*HD];
__device__ uint32_t g_P[(size_t)BH*NN*NN/2];   // bf16 pairs, 256 MB
__device__ float g_rowsum[BH*NN];
__device__ float g_t0[(size_t)BH*NN*HD];
__device__ float g_t1[(size_t)BH*NN*HD];
__device__ float g_acc[(size_t)BH*NN*HD];

__device__ __forceinline__ uint32_t f2tf(float f) {
    uint32_t r;
    asm("cvt.rna.tf32.f32 %0, %1;" : "=r"(r) : "f"(f));
    return r;
}

// pack two fp32 -> bf16x2 (lo in low half, hi in high half)
__device__ __forceinline__ uint32_t pack_bf16(float lo, float hi) {
    uint32_t r;
    asm("cvt.rn.bf16x2.f32 %0, %1, %2;" : "=r"(r) : "f"(hi), "f"(lo));
    return r;
}

__device__ __forceinline__ void mma_tf32(float& d0, float& d1, float& d2, float& d3,
                                         uint32_t a0, uint32_t a1, uint32_t a2, uint32_t a3,
                                         uint32_t b0, uint32_t b1) {
    asm("mma.sync.aligned.m16n8k8.row.col.f32.tf32.tf32.f32 "
        "{%0,%1,%2,%3},{%4,%5,%6,%7},{%8,%9},{%0,%1,%2,%3};"
        : "+f"(d0), "+f"(d1), "+f"(d2), "+f"(d3)
        : "r"(a0), "r"(a1), "r"(a2), "r"(a3), "r"(b0), "r"(b1));
}

__device__ __forceinline__ void mma_bf16(float& d0, float& d1, float& d2, float& d3,
                                         uint32_t a0, uint32_t a1, uint32_t a2, uint32_t a3,
                                         uint32_t b0, uint32_t b1) {
    asm("mma.sync.aligned.m16n8k16.row.col.f32.bf16.bf16.f32 "
        "{%0,%1,%2,%3},{%4,%5,%6,%7},{%8,%9},{%0,%1,%2,%3};"
        : "+f"(d0), "+f"(d1), "+f"(d2), "+f"(d3)
        : "r"(a0), "r"(a1), "r"(a2), "r"(a3), "r"(b0), "r"(b1));
}

// ============================================================
// Kernel 1: QKV projection + head split. (scalar fp32 — small)
// ============================================================
__global__ void qkv_kernel(const float* __restrict__ x,
                           const float* __restrict__ Wq, const float* __restrict__ bq,
                           const float* __restrict__ Wk, const float* __restrict__ bk,
                           const float* __restrict__ Wv, const float* __restrict__ bv,
                           const float* __restrict__ coeffs) {
    const int mat = blockIdx.z;
    const float* W    = (mat == 0) ? Wq : ((mat == 1) ? Wk : Wv);
    const float* bias = (mat == 0) ? bq : ((mat == 1) ? bk : bv);
    const int m0 = blockIdx.x * 64;
    const int c0 = blockIdx.y * 64;

    __shared__ float Xs[64][33];
    __shared__ float Ws[32][64];

    const int tid = threadIdx.x;
    const int ty = tid >> 4, tx = tid & 15;

    float acc[4][4] = {};

    for (int k0 = 0; k0 < DD; k0 += 32) {
        for (int l = tid; l < 512; l += 256) {
            int r = l >> 3, kq = l & 7;
            float4 v = *(const float4*)(x + (size_t)(m0 + r) * DD + k0 + kq * 4);
            Xs[r][kq*4+0] = v.x; Xs[r][kq*4+1] = v.y;
            Xs[r][kq*4+2] = v.z; Xs[r][kq*4+3] = v.w;
        }
        for (int l = tid; l < 512; l += 256) {
            int k = l >> 4, cq = l & 15;
            *(float4*)&Ws[k][cq*4] = *(const float4*)(W + (size_t)(k0 + k) * DD + c0 + cq * 4);
        }
        __syncthreads();
        #pragma unroll
        for (int kk = 0; kk < 32; kk++) {
            float a0 = Xs[ty*4+0][kk];
            float a1 = Xs[ty*4+1][kk];
            float a2 = Xs[ty*4+2][kk];
            float a3 = Xs[ty*4+3][kk];
            float4 b = *(float4*)&Ws[kk][tx*4];
            acc[0][0] += a0*b.x; acc[0][1] += a0*b.y; acc[0][2] += a0*b.z; acc[0][3] += a0*b.w;
            acc[1][0] += a1*b.x; acc[1][1] += a1*b.y; acc[1][2] += a1*b.z; acc[1][3] += a1*b.w;
            acc[2][0] += a2*b.x; acc[2][1] += a2*b.y; acc[2][2] += a2*b.z; acc[2][3] += a2*b.w;
            acc[3][0] += a3*b.x; acc[3][1] += a3*b.y; acc[3][2] += a3*b.z; acc[3][3] += a3*b.w;
        }
        __syncthreads();
    }

    #pragma unroll
    for (int i = 0; i < 4; i++) {
        int m = m0 + ty * 4 + i;
        int b_ = m >> 11, n = m & 2047;
        #pragma unroll
        for (int j = 0; j < 4; j++) {
            int c = c0 + tx * 4 + j;
            float val = acc[i][j] + bias[c];
            int h = c >> 5, d = c & 31;
            size_t idx = ((size_t)(b_ * HH + h) * NN + n) * HD + d;
            if (mat == 0)      g_Q[idx] = val;
            else if (mat == 1) g_K[idx] = val;
            else {
                g_t0[idx]  = val;
                g_acc[idx] = coeffs[h * 4] * val;   // c0 * v
            }
        }
    }
}

// ============================================================
// Kernel 2: P = exp(Q K^T * scale) via tf32 mma, store bf16 pairs + rowsums.
// grid (16 row-tiles of 128, 32 bh), block 256 (8 warps).
// ============================================================
__global__ void attnP_kernel() {
    const int bh = blockIdx.y;
    const int r0 = blockIdx.x * 128;

    __shared__ uint32_t Qs[128][36];   // tf32 bits
    __shared__ uint32_t Ks[128][36];

    const int tid  = threadIdx.x;
    const int warp = tid >> 5;
    const int lane = tid & 31;
    const int g  = lane >> 2;   // 0..7
    const int qd = lane & 3;    // 0..3

    const float scale = 0.17677669529663687f;  // 1/sqrt(32), folded into Q

    const float* Qb = g_Q + ((size_t)bh * NN + r0) * HD;
    for (int l = tid; l < 1024; l += 256) {
        int r = l >> 3, kq = l & 7;
        float4 v = *(const float4*)(Qb + (size_t)r * HD + kq * 4);
        uint4 u;
        u.x = f2tf(v.x * scale); u.y = f2tf(v.y * scale);
        u.z = f2tf(v.z * scale); u.w = f2tf(v.w * scale);
        *(uint4*)&Qs[r][kq*4] = u;
    }
    __syncthreads();

    const int row_l = warp * 16 + g;
    float rs_lo = 0.f, rs_hi = 0.f;

    for (int ct = 0; ct < 16; ct++) {
        const int c0 = ct * 128;
        const float* Kb = g_K + ((size_t)bh * NN + c0) * HD;
        for (int l = tid; l < 1024; l += 256) {
            int r = l >> 3, kq = l & 7;
            float4 v = *(const float4*)(Kb + (size_t)r * HD + kq * 4);
            uint4 u;
            u.x = f2tf(v.x); u.y = f2tf(v.y);
            u.z = f2tf(v.z); u.w = f2tf(v.w);
            *(uint4*)&Ks[r][kq*4] = u;
        }
        __syncthreads();

        float acc[16][4];
        #pragma unroll
        for (int j = 0; j < 16; j++) {
            acc[j][0] = 0.f; acc[j][1] = 0.f; acc[j][2] = 0.f; acc[j][3] = 0.f;
        }

        #pragma unroll
        for (int kc = 0; kc < 32; kc += 8) {
            uint32_t a0 = Qs[row_l    ][kc + qd];
            uint32_t a1 = Qs[row_l + 8][kc + qd];
            uint32_t a2 = Qs[row_l    ][kc + qd + 4];
            uint32_t a3 = Qs[row_l + 8][kc + qd + 4];
            #pragma unroll
            for (int j = 0; j < 16; j++) {
                uint32_t b0 = Ks[j*8 + g][kc + qd];
                uint32_t b1 = Ks[j*8 + g][kc + qd + 4];
                mma_tf32(acc[j][0], acc[j][1], acc[j][2], acc[j][3],
                         a0, a1, a2, a3, b0, b1);
            }
        }

        // epilogue: exp, pack bf16 pairs, store, rowsum partials
        uint32_t* Pb = g_P + (((size_t)bh * NN + r0) * NN + c0) / 2;
        #pragma unroll
        for (int j = 0; j < 16; j++) {
            int colp = (j*8 + qd*2) >> 1;            // pair index within 128-col chunk
            float e0 = __expf(acc[j][0]);
            float e1 = __expf(acc[j][1]);
            float e2 = __expf(acc[j][2]);
            float e3 = __expf(acc[j][3]);
            Pb[(size_t)(row_l    ) * (NN/2) + colp] = pack_bf16(e0, e1);
            Pb[(size_t)(row_l + 8) * (NN/2) + colp] = pack_bf16(e2, e3);
            rs_lo += e0 + e1;
            rs_hi += e2 + e3;
        }
        __syncthreads();
    }

    rs_lo += __shfl_xor_sync(0xffffffffu, rs_lo, 1);
    rs_lo += __shfl_xor_sync(0xffffffffu, rs_lo, 2);
    rs_hi += __shfl_xor_sync(0xffffffffu, rs_hi, 1);
    rs_hi += __shfl_xor_sync(0xffffffffu, rs_hi, 2);
    if (qd == 0) {
        g_rowsum[bh * NN + r0 + row_l]     = rs_lo;
        g_rowsum[bh * NN + r0 + row_l + 8] = rs_hi;
    }
}

// ============================================================
// Kernel 3: t_out = diag(1/rowsum) * P * t_in ; g_acc += c_k * t_out
// bf16 mma m16n8k16. grid (16 row-tiles of 128, 32 bh), block 256 (8 warps).
// m-chunks of 128. P staged as raw bf16 pairs (no conversion).
// ============================================================
__global__ void pass_kernel(const float* __restrict__ coeffs, int pass) {
    const float* tin  = (pass & 1) ? g_t0 : g_t1;
    float*       tout = (pass & 1) ? g_t1 : g_t0;

    const int bh = blockIdx.y;
    const int r0 = blockIdx.x * 128;
    const float c = coeffs[(bh & 7) * 4 + pass];

    __shared__ uint32_t Ps[128][68];   // bf16 pairs along m; A-frag bank = (4g+qd) ok
    __shared__ uint32_t Ts[64][40];    // bf16 pairs along m; B-frag bank = (8qd+g) ok

    const int tid  = threadIdx.x;
    const int warp = tid >> 5;
    const int lane = tid & 31;
    const int g  = lane >> 2;
    const int qd = lane & 3;

    float acc[4][4];
    #pragma unroll
    for (int j = 0; j < 4; j++) {
        acc[j][0] = 0.f; acc[j][1] = 0.f; acc[j][2] = 0.f; acc[j][3] = 0.f;
    }

    const uint32_t* Prow = g_P + ((size_t)bh * NN + r0) * (NN/2);
    const float* Tb = tin + (size_t)bh * NN * HD;
    const int row_l = warp * 16 + g;

    for (int m0 = 0; m0 < NN; m0 += 128) {
        // stage P tile 128 rows x 64 uint32 (128 bf16): 2048 uint4, raw copy
        for (int l = tid; l < 2048; l += 256) {
            int r = l >> 4, mq = l & 15;
            *(uint4*)&Ps[r][mq*4] =
                *(const uint4*)(Prow + (size_t)r * (NN/2) + m0/2 + mq*4);
        }
        // stage t tile 128x32 fp32 -> 64 pair-rows x 32 cols bf16x2
        for (int l = tid; l < 512; l += 256) {
            int m2 = l >> 3, cq = l & 7;
            float4 v0 = *(const float4*)(Tb + (size_t)(m0 + 2*m2    ) * HD + cq * 4);
            float4 v1 = *(const float4*)(Tb + (size_t)(m0 + 2*m2 + 1) * HD + cq * 4);
            Ts[m2][cq*4+0] = pack_bf16(v0.x, v1.x);
            Ts[m2][cq*4+1] = pack_bf16(v0.y, v1.y);
            Ts[m2][cq*4+2] = pack_bf16(v0.z, v1.z);
            Ts[m2][cq*4+3] = pack_bf16(v0.w, v1.w);
        }
        __syncthreads();

        #pragma unroll
        for (int kc = 0; kc < 64; kc += 8) {       // kc in pair units (16 bf16 per step)
            uint32_t a0 = Ps[row_l    ][kc + qd];
            uint32_t a1 = Ps[row_l + 8][kc + qd];
            uint32_t a2 = Ps[row_l    ][kc + qd + 4];
            uint32_t a3 = Ps[row_l + 8][kc + qd + 4];
            #pragma unroll
            for (int j = 0; j < 4; j++) {
                uint32_t b0 = Ts[kc + qd    ][j*8 + g];
                uint32_t b1 = Ts[kc + qd + 4][j*8 + g];
                mma_bf16(acc[j][0], acc[j][1], acc[j][2], acc[j][3],
                         a0, a1, a2, a3, b0, b1);
            }
        }
        __syncthreads();
    }

    const int r_lo = r0 + row_l;
    const int r_hi = r_lo + 8;
    const float inv_lo = 1.0f / g_rowsum[bh * NN + r_lo];
    const float inv_hi = 1.0f / g_rowsum[bh * NN + r_hi];
    #pragma unroll
    for (int j = 0; j < 4; j++) {
        int col = j*8 + qd*2;
        size_t o_lo = ((size_t)bh * NN + r_lo) * HD + col;
        size_t o_hi = ((size_t)bh * NN + r_hi) * HD + col;
        float2 lo = make_float2(acc[j][0] * inv_lo, acc[j][1] * inv_lo);
        float2 hi = make_float2(acc[j][2] * inv_hi, acc[j][3] * inv_hi);
        *(float2*)(tout + o_lo) = lo;
        *(float2*)(tout + o_hi) = hi;
        float2 a_lo = *(float2*)(g_acc + o_lo);
        float2 a_hi = *(float2*)(g_acc + o_hi);
        a_lo.x += c * lo.x; a_lo.y += c * lo.y;
        a_hi.x += c * hi.x; a_hi.y += c * hi.y;
        *(float2*)(g_acc + o_lo) = a_lo;
        *(float2*)(g_acc + o_hi) = a_hi;
    }
}

// ============================================================
// Kernel 4: out = merged(g_acc) @ Wo + bo  (scalar fp32 — small)
// ============================================================
__global__ void outproj_kernel(const float* __restrict__ Wo,
                               const float* __restrict__ bo,
                               float* __restrict__ out) {
    const int m0 = blockIdx.x * 64;
    const int c0 = blockIdx.y * 64;

    __shared__ float Ms[64][33];
    __shared__ float Ws[32][64];

    const int tid = threadIdx.x;
    const int ty = tid >> 4, tx = tid & 15;

    float acc[4][4] = {};

    for (int k0 = 0; k0 < DD; k0 += 32) {
        int hh = k0 >> 5;
        for (int l = tid; l < 512; l += 256) {
            int r = l >> 3, kq = l & 7;
            int m = m0 + r;
            int b_ = m >> 11, n = m & 2047;
            float4 v = *(const float4*)(g_acc + ((size_t)(b_ * HH + hh) * NN + n) * HD + kq * 4);
            Ms[r][kq*4+0] = v.x; Ms[r][kq*4+1] = v.y;
            Ms[r][kq*4+2] = v.z; Ms[r][kq*4+3] = v.w;
        }
        for (int l = tid; l < 512; l += 256) {
            int k = l >> 4, cq = l & 15;
            *(float4*)&Ws[k][cq*4] = *(const float4*)(Wo + (size_t)(k0 + k) * DD + c0 + cq * 4);
        }
        __syncthreads();
        #pragma unroll
        for (int kk = 0; kk < 32; kk++) {
            float a0 = Ms[ty*4+0][kk];
            float a1 = Ms[ty*4+1][kk];
            float a2 = Ms[ty*4+2][kk];
            float a3 = Ms[ty*4+3][kk];
            float4 b = *(float4*)&Ws[kk][tx*4];
            acc[0][0] += a0*b.x; acc[0][1] += a0*b.y; acc[0][2] += a0*b.z; acc[0][3] += a0*b.w;
            acc[1][0] += a1*b.x; acc[1][1] += a1*b.y; acc[1][2] += a1*b.z; acc[1][3] += a1*b.w;
            acc[2][0] += a2*b.x; acc[2][1] += a2*b.y; acc[2][2] += a2*b.z; acc[2][3] += a2*b.w;
            acc[3][0] += a3*b.x; acc[3][1] += a3*b.y; acc[3][2] += a3*b.z; acc[3][3] += a3*b.w;
        }
        __syncthreads();
    }

    #pragma unroll
    for (int i = 0; i < 4; i++) {
        int m = m0 + ty * 4 + i;
        #pragma unroll
        for (int j = 0; j < 4; j++) {
            int cc = c0 + tx * 4 + j;
            out[(size_t)m * DD + cc] = acc[i][j] + bo[cc];
        }
    }
}

// ============================================================
extern "C" void kernel_launch(void* const* d_in, const int* in_sizes, int n_in,
                              void* d_out, int out_size) {
    const float* x      = (const float*)d_in[0];
    const float* Wq     = (const float*)d_in[1];
    const float* bq     = (const float*)d_in[2];
    const float* Wk     = (const float*)d_in[3];
    const float* bk     = (const float*)d_in[4];
    const float* Wv     = (const float*)d_in[5];
    const float* bv     = (const float*)d_in[6];
    const float* Wo     = (const float*)d_in[7];
    const float* bo     = (const float*)d_in[8];
    const float* coeffs = (const float*)d_in[9];
    float* out = (float*)d_out;

    dim3 g1(128, 4, 3);
    qkv_kernel<<<g1, 256>>>(x, Wq, bq, Wk, bk, Wv, bv, coeffs);

    dim3 g2(16, 32);
    attnP_kernel<<<g2, 256>>>();

    pass_kernel<<<g2, 256>>>(coeffs, 1);
    pass_kernel<<<g2, 256>>>(coeffs, 2);
    pass_kernel<<<g2, 256>>>(coeffs, 3);

    dim3 g4(128, 4);
    outproj_kernel<<<g4, 256>>>(Wo, bo, out);
}